// round 8
// baseline (speedup 1.0000x reference)
#include <cuda_runtime.h>
#include <cstdint>

// Problem dims
constexpr int BATCH = 64;
constexpr int SEQ   = 512;
constexpr int EMB   = 256;
constexpr int HID   = 512;
constexpr int OUTD  = 1000;
constexpr int KD    = HID + EMB;   // 768

// Persistent-kernel config
constexpr int NCTA     = 128;           // 1 CTA per SM, all resident -> spin barrier safe
constexpr int UNITS    = HID / NCTA;    // 4 hidden units per CTA
constexpr int NCOLS    = 4 * UNITS;     // 16 gate columns (f,i,c,o x units)
constexpr int NTHREADS = 512;           // 16 warps = 4 per SMSP
constexpr int NTEAMS   = 4;             // 128-thread teams
constexpr int TEAM_T   = 128;
constexpr int CHUNK_K  = 64;            // team t owns k-chunks {64t, 256+64t (h), 512+64t (emb)}
constexpr int CPAD     = CHUNK_K + 4;   // 68: float4-aligned, 4-bank row skew
constexpr int WPAD     = KD + 4;        // 772: float4-aligned, 4-bank col skew
constexpr int TEAM_BUF = BATCH * CPAD;  // 4352 floats per staging buffer
constexpr int GPITCH   = NCOLS + 1;     // 17: odd pitch for reduce STS
constexpr int FSTRIDE  = 32;            // one flag per 128B line (32 uints)

typedef unsigned long long u64;

// Device scratch (static — no runtime allocs allowed)
__device__ float g_emb[SEQ * BATCH * EMB];         // [s][b][e]
__device__ float g_hbuf[2][BATCH * HID];           // double-buffered hidden state
__device__ unsigned int g_flags[NCTA * FSTRIDE];   // distributed barrier flags
// Flags are MONOTONIC epochs: zero-initialized at module load; each launch
// reads its own flag as `base` and writes base+1 .. base+513. All flags end
// the launch equal, so the next graph replay re-bases cleanly. No reset race.

__device__ __forceinline__ void fma2(u64 &d, u64 a, u64 b) {
    asm("fma.rn.f32x2 %0, %1, %2, %0;" : "+l"(d) : "l"(a), "l"(b));
}
__device__ __forceinline__ float pairsum(u64 v) {
    float lo, hi;
    asm("mov.b64 {%0,%1}, %2;" : "=f"(lo), "=f"(hi) : "l"(v));
    return lo + hi;
}
__device__ __forceinline__ float sigf(float x) { return 1.0f / (1.0f + expf(-x)); }

__device__ __forceinline__ void cp16(float* smem_dst, const float* gsrc) {
    uint32_t sa = (uint32_t)__cvta_generic_to_shared(smem_dst);
    asm volatile("cp.async.cg.shared.global [%0], [%1], 16;" :: "r"(sa), "l"(gsrc));
}
__device__ __forceinline__ void cp_commit()  { asm volatile("cp.async.commit_group;" ::: "memory"); }
__device__ __forceinline__ void cp_wait0()   { asm volatile("cp.async.wait_group 0;" ::: "memory"); }
__device__ __forceinline__ void cp_wait1()   { asm volatile("cp.async.wait_group 1;" ::: "memory"); }

// Named barrier scoped to one 128-thread team (ids 1..4; 0 is __syncthreads)
__device__ __forceinline__ void team_bar(int id) {
    asm volatile("bar.sync %0, %1;" :: "r"(id), "n"(TEAM_T) : "memory");
}

// ---------------------------------------------------------------------------
// ONE persistent kernel: embed prologue -> 512-step LSTM loop -> dense epilogue.
// Distributed flag barrier (no central atomic):
//   arrive: tid0 does __threadfence() then volatile-stores its epoch to
//           g_flags[cta*FSTRIDE] (one 128B line per CTA -> no LTS hot spot).
//   wait:   threads tid<NCTA spin-read flag[tid] (128 distinct lines, fully
//           parallel ~260cyc) until >= target, then __syncthreads().
// Epoch ledger (relative to base): embed=+1, step s=+2+s, dense waits >= +513.
// ---------------------------------------------------------------------------
__global__ void __launch_bounds__(NTHREADS, 1)
lstm_all_kernel(const int*   __restrict__ x,  const float* __restrict__ ew,
                const float* __restrict__ h0, const float* __restrict__ c0,
                const float* __restrict__ Wf, const float* __restrict__ bf,
                const float* __restrict__ Wi, const float* __restrict__ bi,
                const float* __restrict__ Wc, const float* __restrict__ bc,
                const float* __restrict__ Wo, const float* __restrict__ bo,
                const float* __restrict__ Wd, const float* __restrict__ bd,
                float* __restrict__ out)
{
    extern __shared__ float smem[];
    float* s_w    = smem;                                   // 16*772          = 12352
    float* s_comb = s_w + NCOLS * WPAD;                     // 4 teams*2*4352  = 34816
    float* s_g    = s_comb + NTEAMS * 2 * TEAM_BUF;         // 4*64*17         = 4352
    float* s_b    = s_g + NTEAMS * BATCH * GPITCH;          // 16
    __shared__ unsigned int s_base;                         // launch epoch base

    const int tid = threadIdx.x;
    const int cta = blockIdx.x;
    const int j0  = cta * UNITS;

    // --- epoch base: my own flag's value at launch (all flags equal here) ---
    if (tid == 0) s_base = *((volatile unsigned int*)&g_flags[cta * FSTRIDE]);

    // ---------------- prologue: weights + biases into SMEM ----------------
    for (int idx = tid; idx < NCOLS * KD; idx += NTHREADS) {
        int col = idx / KD;
        int k   = idx - col * KD;
        int u   = col & 3;
        const float* W = (col < 4) ? Wf : (col < 8) ? Wi : (col < 12) ? Wc : Wo;
        s_w[col * WPAD + k] = W[k * HID + j0 + u];
    }
    if (tid < NCOLS) {
        int u = tid & 3;
        const float* Bp = (tid < 4) ? bf : (tid < 8) ? bi : (tid < 12) ? bc : bo;
        s_b[tid] = Bp[j0 + u];
    }

    // ---------------- prologue: embedding gather (CTA slice) ----------------
    {
        const int PER_CTA = (SEQ * BATCH * EMB / 4) / NCTA;   // 16384 float4
        int base = cta * PER_CTA;
        #pragma unroll 4
        for (int n = 0; n < PER_CTA / NTHREADS; ++n) {        // 32 iters
            int i  = base + tid + n * NTHREADS;
            int e4 = i & 63;                                   // EMB/4 = 64
            int b  = (i >> 6) & 63;
            int s  = i >> 12;
            int tok = x[b * SEQ + s];
            float4 v = reinterpret_cast<const float4*>(ew + (long)tok * EMB)[e4];
            reinterpret_cast<float4*>(g_emb + ((long)s * BATCH + b) * EMB)[e4] = v;
        }
    }

    // --- activation role (tid < 256): thread owns (b=ab, unit=au) ---
    const int ab = tid >> 2;
    const int au = tid & 3;
    float c_reg = 0.0f;
    if (tid < 256) c_reg = c0[ab * HID + j0 + au];

    // --- compute role: team over K, 4b x 2c register tile ---
    const int team  = tid >> 7;         // 0..3
    const int tt    = tid & 127;
    const int tx    = tt & 7;           // cols {tx, tx+8}
    const int ty    = tt >> 3;          // batches {ty, ty+16, ty+32, ty+48}
    const int bid   = 1 + team;         // named barrier id
    float* buf0 = s_comb + team * 2 * TEAM_BUF;
    float* buf1 = buf0 + TEAM_BUF;
    float* gslab = s_g + team * (BATCH * GPITCH);

    auto stage_async = [&](float* dst, const float* src, int stride, int k0) {
        #pragma unroll
        for (int n = 0; n < 8; ++n) {
            int i   = tt + TEAM_T * n;
            int row = i >> 4;
            int q   = i & 15;
            cp16(dst + row * CPAD + (q << 2), src + row * stride + k0 + (q << 2));
        }
    };

    u64 acc[4][2];
    auto compute = [&](const float* cbuf, int kg0, int kbeg, int kend) {
        #pragma unroll 4
        for (int kk = kbeg; kk < kend; kk += 4) {
            ulonglong2 w0 = *reinterpret_cast<const ulonglong2*>(s_w + (tx    ) * WPAD + kg0 + kk);
            ulonglong2 w1 = *reinterpret_cast<const ulonglong2*>(s_w + (tx + 8) * WPAD + kg0 + kk);
            #pragma unroll
            for (int r = 0; r < 4; ++r) {
                ulonglong2 cb = *reinterpret_cast<const ulonglong2*>(cbuf + (r * 16 + ty) * CPAD + kk);
                fma2(acc[r][0], cb.x, w0.x); fma2(acc[r][0], cb.y, w0.y);
                fma2(acc[r][1], cb.x, w1.x); fma2(acc[r][1], cb.y, w1.y);
            }
        }
    };

    // barrier primitives (s_base valid after the first __syncthreads below)
    auto flag_arrive = [&](unsigned rel) {        // caller: tid==0, post-sync
        __threadfence();                          // cumulative release
        *((volatile unsigned int*)&g_flags[cta * FSTRIDE]) = s_base + rel;
    };
    auto flag_spin = [&](unsigned rel) {          // caller: tid < NCTA
        unsigned tgt = s_base + rel;
        while (*((volatile unsigned int*)&g_flags[tid * FSTRIDE]) < tgt) { }
    };

    // ---------------- embed barrier (epoch +1) ----------------
    __syncthreads();                 // g_emb stores + s_base + s_w/s_b visible
    if (tid == 0) flag_arrive(1u);
    if (tid < NCTA) flag_spin(1u);
    __syncthreads();

    // prefetch emb chunk for s=0 into buf0 (g_emb now complete)
    stage_async(buf0, g_emb, EMB, CHUNK_K * team);
    cp_commit();       // pending: {emb_0}

    // ---------------- recurrent loop ----------------
    for (int s = 0; s < SEQ; ++s) {
        const float* hc   = (s == 0) ? h0 : g_hbuf[s & 1];
        const int    e    = s & 1;
        float* bufE = e ? buf1 : buf0;   // holds emb_s (prefetched)
        float* bufH = e ? buf0 : buf1;   // stale, free to overwrite

        #pragma unroll
        for (int r = 0; r < 4; ++r) { acc[r][0] = 0ULL; acc[r][1] = 0ULL; }

        const int kgE = HID + CHUNK_K * team;
        const int kgA = CHUNK_K * team;
        const int kgB = 256 + CHUNK_K * team;

        // ---- emb PART1 (barrier-independent; absorbs skew) ----
        cp_wait0();
        team_bar(bid);
        compute(bufE, kgE, 0, CHUNK_K / 2);

        // ---- barrier WAIT: all CTAs passed step s-1 (epoch +1+s) ----
        if (s > 0 && tid < NCTA) flag_spin(1u + (unsigned)s);
        __syncthreads();

        // ---- issue hA; emb PART2 hides its latency ----
        stage_async(bufH, hc, HID, kgA);     // pending: {hA}
        cp_commit();
        compute(bufE, kgE, CHUNK_K / 2, CHUNK_K);
        team_bar(bid);                   // team done reading bufE

        // ---- issue hB into bufE; hA compute hides its latency ----
        stage_async(bufE, hc, HID, kgB);     // pending: {hA, hB}
        cp_commit();

        cp_wait1();                      // hA landed
        team_bar(bid);
        compute(bufH, kgA, 0, CHUNK_K);
        team_bar(bid);                   // team done reading bufH

        // ---- prefetch next emb into bufH ----
        {
            int sn = (s + 1 < SEQ) ? s + 1 : s;
            stage_async(bufH, g_emb + (long)sn * (BATCH * EMB), EMB, CHUNK_K * team);
            cp_commit();                 // pending: {hB, embN}
        }

        cp_wait1();                      // hB landed
        team_bar(bid);
        compute(bufE, kgB, 0, CHUNK_K);

        // ---- per-team partial sums -> SMEM slabs ----
        #pragma unroll
        for (int r = 0; r < 4; ++r) {
            int brow = r * 16 + ty;
            gslab[brow * GPITCH + tx    ] = pairsum(acc[r][0]);
            gslab[brow * GPITCH + tx + 8] = pairsum(acc[r][1]);
        }
        __syncthreads();

        // ---- activation + state update by owning (b,u) thread ----
        if (tid < 256) {
            const int base = ab * GPITCH;
            const int T = BATCH * GPITCH;
            float pre_f = s_b[au]
                        + s_g[base + au] + s_g[T + base + au] + s_g[2*T + base + au] + s_g[3*T + base + au];
            float pre_i = s_b[4 + au]
                        + s_g[base+4+au] + s_g[T + base+4+au] + s_g[2*T + base+4+au] + s_g[3*T + base+4+au];
            float pre_c = s_b[8 + au]
                        + s_g[base+8+au] + s_g[T + base+8+au] + s_g[2*T + base+8+au] + s_g[3*T + base+8+au];
            float pre_o = s_b[12 + au]
                        + s_g[base+12+au] + s_g[T + base+12+au] + s_g[2*T + base+12+au] + s_g[3*T + base+12+au];
            float fg = sigf(pre_f);
            float ig = sigf(pre_i);
            float cg = tanhf(pre_c);
            float og = sigf(pre_o);
            c_reg = fg * c_reg + ig * cg;
            float hval = og * tanhf(c_reg);
            g_hbuf[(s + 1) & 1][ab * HID + j0 + au] = hval;
            if (s == SEQ - 1) out[BATCH * OUTD + ab * HID + j0 + au] = hval;
        }
        __syncthreads();                 // h writes block-visible

        // ---- barrier ARRIVE (epoch +2+s; wait deferred to next step) ----
        if (tid == 0) flag_arrive(2u + (unsigned)s);
    }

    cp_wait0();   // drain the final (unused) emb prefetch

    // ---------------- dense epilogue ----------------
    // wait for all CTAs' final h (epoch +2+511 = +513)
    if (tid < NCTA) flag_spin(513u);
    __syncthreads();

    {
        // CTA handles output cols [cta*8, cta*8+8) ; thread = (b, c8)
        const int c8  = tid & 7;
        const int b   = tid >> 3;          // 0..63
        const int col = cta * 8 + c8;
        if (col < OUTD) {
            const float4* hrow = reinterpret_cast<const float4*>(g_hbuf[0] + b * HID);
            float acc4 = bd[col];
            #pragma unroll 4
            for (int q = 0; q < HID / 4; ++q) {
                float4 hv = __ldcv(hrow + q);   // .cv: bypass L1 (h written by other CTAs)
                int k = q << 2;
                acc4 += hv.x * Wd[(k    ) * OUTD + col]
                      + hv.y * Wd[(k + 1) * OUTD + col]
                      + hv.z * Wd[(k + 2) * OUTD + col]
                      + hv.w * Wd[(k + 3) * OUTD + col];
            }
            out[b * OUTD + col] = acc4;
        }
    }
    // All flags end at base+513 (equal) -> next graph replay re-bases cleanly.
}

// ---------------------------------------------------------------------------
extern "C" void kernel_launch(void* const* d_in, const int* in_sizes, int n_in,
                              void* d_out, int out_size)
{
    const int*   x      = (const int*)  d_in[0];
    const float* hidden = (const float*)d_in[1];
    const float* c      = (const float*)d_in[2];
    const float* ew     = (const float*)d_in[3];
    const float* Wf     = (const float*)d_in[4];
    const float* bf     = (const float*)d_in[5];
    const float* Wi     = (const float*)d_in[6];
    const float* bi     = (const float*)d_in[7];
    const float* Wc     = (const float*)d_in[8];
    const float* bc     = (const float*)d_in[9];
    const float* Wo     = (const float*)d_in[10];
    const float* bo     = (const float*)d_in[11];
    const float* Wd     = (const float*)d_in[12];
    const float* bd     = (const float*)d_in[13];
    float* out = (float*)d_out;   // [B*OUTD output][B*HID hidden]

    const size_t smem_bytes =
        (size_t)(NCOLS * WPAD + NTEAMS * 2 * TEAM_BUF + NTEAMS * BATCH * GPITCH + NCOLS) * sizeof(float);
    cudaFuncSetAttribute(lstm_all_kernel, cudaFuncAttributeMaxDynamicSharedMemorySize, (int)smem_bytes);
    lstm_all_kernel<<<NCTA, NTHREADS, smem_bytes>>>(x, ew, hidden, c,
                                                    Wf, bf, Wi, bi, Wc, bc, Wo, bo,
                                                    Wd, bd, out);
}

// round 10
// speedup vs baseline: 1.1806x; 1.1806x over previous
#include <cuda_runtime.h>
#include <cstdint>

// Problem dims
constexpr int BATCH = 64;
constexpr int SEQ   = 512;
constexpr int EMB   = 256;
constexpr int HID   = 512;
constexpr int OUTD  = 1000;
constexpr int KD    = HID + EMB;   // 768

// Persistent-kernel config
constexpr int NCTA     = 128;           // 1 CTA per SM, all resident -> spin barrier safe
constexpr int UNITS    = HID / NCTA;    // 4 hidden units per CTA
constexpr int NCOLS    = 4 * UNITS;     // 16 gate columns (f,i,c,o x units)
constexpr int NTHREADS = 256;           // 8 warps
constexpr int NTEAMS   = 4;             // 64-thread teams
constexpr int TEAM_T   = 64;
constexpr int CHUNK_K  = 64;            // team t owns k-chunks {64t, 256+64t (h), 512+64t (emb)}
constexpr int CPAD     = CHUNK_K + 4;   // 68: float4-aligned, 4-bank row skew
constexpr int WPAD     = KD + 4;        // 772: float4-aligned, 4-bank col skew
constexpr int TEAM_BUF = BATCH * CPAD;  // 4352 floats per staging buffer
constexpr int GPITCH   = NCOLS + 1;     // 17

typedef unsigned long long u64;

// Device scratch (static — no runtime allocs allowed)
__device__ float g_emb[SEQ * BATCH * EMB];     // [s][b][e]
__device__ float g_hbuf[2][BATCH * HID];       // double-buffered hidden state
__device__ unsigned int g_bar;                 // central barrier counter (reset to 0 on exit)

__device__ __forceinline__ void fma2(u64 &d, u64 a, u64 b) {
    asm("fma.rn.f32x2 %0, %1, %2, %0;" : "+l"(d) : "l"(a), "l"(b));
}
__device__ __forceinline__ float pairsum(u64 v) {
    float lo, hi;
    asm("mov.b64 {%0,%1}, %2;" : "=f"(lo), "=f"(hi) : "l"(v));
    return lo + hi;
}
__device__ __forceinline__ float sigf(float x) { return 1.0f / (1.0f + expf(-x)); }

__device__ __forceinline__ void cp16(float* smem_dst, const float* gsrc) {
    uint32_t sa = (uint32_t)__cvta_generic_to_shared(smem_dst);
    asm volatile("cp.async.cg.shared.global [%0], [%1], 16;" :: "r"(sa), "l"(gsrc));
}
__device__ __forceinline__ void cp_commit()  { asm volatile("cp.async.commit_group;" ::: "memory"); }
__device__ __forceinline__ void cp_wait0()   { asm volatile("cp.async.wait_group 0;" ::: "memory"); }
__device__ __forceinline__ void cp_wait1()   { asm volatile("cp.async.wait_group 1;" ::: "memory"); }

// Named barrier scoped to one 64-thread team (ids 1..4; 0 is __syncthreads)
__device__ __forceinline__ void team_bar(int id) {
    asm volatile("bar.sync %0, %1;" :: "r"(id), "n"(TEAM_T) : "memory");
}

// Central atomic barrier (cumulative count; single spinner = tid0)
__device__ __forceinline__ void grid_arrive() { atomicAdd(&g_bar, 1u); }
__device__ __forceinline__ void grid_spin(unsigned target) {
    while (*((volatile unsigned int*)&g_bar) < target) { }
}

// ---------------------------------------------------------------------------
// ONE persistent kernel: embed prologue -> 512-step LSTM loop -> dense epilogue.
// Ledger (cumulative, per-CTA arrivals): embed -> NCTA; step s -> (s+2)*NCTA;
// dense -> 514*NCTA; cta0 spins 514*NCTA then resets g_bar=0 (graph-replay safe).
// Release at every arrival: __syncthreads -> tid0 __threadfence (cumulative) ->
// atomicAdd. Readers consume h via cp.async.cg (L2-direct) or __ldcv.
// Compute: 4 teams x 64 thr; per-thread 4b x 4c x 64k tile, f32x2-packed:
// 8 LDS.128 per 32 FFMA2 -> L1tex wavefronts/step 3072 (below 6144-cyc FMA floor).
// ---------------------------------------------------------------------------
__global__ void __launch_bounds__(NTHREADS, 1)
lstm_all_kernel(const int*   __restrict__ x,  const float* __restrict__ ew,
                const float* __restrict__ h0, const float* __restrict__ c0,
                const float* __restrict__ Wf, const float* __restrict__ bf,
                const float* __restrict__ Wi, const float* __restrict__ bi,
                const float* __restrict__ Wc, const float* __restrict__ bc,
                const float* __restrict__ Wo, const float* __restrict__ bo,
                const float* __restrict__ Wd, const float* __restrict__ bd,
                float* __restrict__ out)
{
    extern __shared__ float smem[];
    float* s_w    = smem;                                   // 16*772   = 12352
    float* s_comb = s_w + NCOLS * WPAD;                     // 4*2*4352 = 34816
    float* s_g    = s_comb + NTEAMS * 2 * TEAM_BUF;         // 4*64*17  = 4352
    float* s_b    = s_g + NTEAMS * BATCH * GPITCH;          // 16
    // total 51536 floats = 206144 bytes

    const int tid = threadIdx.x;
    const int cta = blockIdx.x;
    const int j0  = cta * UNITS;

    // ---------------- prologue: weights + biases into SMEM ----------------
    for (int idx = tid; idx < NCOLS * KD; idx += NTHREADS) {
        int col = idx / KD;
        int k   = idx - col * KD;
        int u   = col & 3;
        const float* W = (col < 4) ? Wf : (col < 8) ? Wi : (col < 12) ? Wc : Wo;
        s_w[col * WPAD + k] = W[k * HID + j0 + u];
    }
    if (tid < NCOLS) {
        int u = tid & 3;
        const float* Bp = (tid < 4) ? bf : (tid < 8) ? bi : (tid < 12) ? bc : bo;
        s_b[tid] = Bp[j0 + u];
    }

    // ---------------- prologue: embedding gather (CTA slice) ----------------
    {
        const int PER_CTA = (SEQ * BATCH * EMB / 4) / NCTA;   // 16384 float4
        int base = cta * PER_CTA;
        #pragma unroll 4
        for (int n = 0; n < PER_CTA / NTHREADS; ++n) {        // 64 iters
            int i  = base + tid + n * NTHREADS;
            int e4 = i & 63;                                   // EMB/4 = 64
            int b  = (i >> 6) & 63;
            int s  = i >> 12;
            int tok = x[b * SEQ + s];
            float4 v = reinterpret_cast<const float4*>(ew + (long)tok * EMB)[e4];
            reinterpret_cast<float4*>(g_emb + ((long)s * BATCH + b) * EMB)[e4] = v;
        }
    }

    // --- activation role: thread owns (b=ab, unit=au) ---
    const int ab = tid >> 2;            // 0..63
    const int au = tid & 3;
    float c_reg = c0[ab * HID + j0 + au];

    // --- compute role: team over K, 4b x 4c register tile ---
    const int team  = tid >> 6;         // 0..3
    const int tt    = tid & 63;
    const int tx    = tt & 3;           // cols {tx, tx+4, tx+8, tx+12}
    const int ty    = tt >> 2;          // 0..15 ; batches {ty, ty+16, ty+32, ty+48}
    const int bid   = 1 + team;         // named barrier id
    float* buf0 = s_comb + team * 2 * TEAM_BUF;
    float* buf1 = buf0 + TEAM_BUF;
    float* gslab = s_g + team * (BATCH * GPITCH);

    // stage one [64 x 64] chunk via cp.async (16 x 16B per thread, team-coop)
    auto stage_async = [&](float* dst, const float* src, int stride, int k0) {
        #pragma unroll 4
        for (int n = 0; n < 16; ++n) {
            int i   = tt + TEAM_T * n;          // 0..1023
            int row = i >> 4;
            int q   = i & 15;
            cp16(dst + row * CPAD + (q << 2), src + row * stride + k0 + (q << 2));
        }
    };

    u64 acc[4][4];
    auto compute = [&](const float* cbuf, int kg0, int kbeg, int kend) {
        #pragma unroll 4
        for (int kk = kbeg; kk < kend; kk += 4) {
            ulonglong2 w0 = *reinterpret_cast<const ulonglong2*>(s_w + (tx     ) * WPAD + kg0 + kk);
            ulonglong2 w1 = *reinterpret_cast<const ulonglong2*>(s_w + (tx +  4) * WPAD + kg0 + kk);
            ulonglong2 w2 = *reinterpret_cast<const ulonglong2*>(s_w + (tx +  8) * WPAD + kg0 + kk);
            ulonglong2 w3 = *reinterpret_cast<const ulonglong2*>(s_w + (tx + 12) * WPAD + kg0 + kk);
            #pragma unroll
            for (int r = 0; r < 4; ++r) {
                ulonglong2 cb = *reinterpret_cast<const ulonglong2*>(cbuf + (r * 16 + ty) * CPAD + kk);
                fma2(acc[r][0], cb.x, w0.x); fma2(acc[r][0], cb.y, w0.y);
                fma2(acc[r][1], cb.x, w1.x); fma2(acc[r][1], cb.y, w1.y);
                fma2(acc[r][2], cb.x, w2.x); fma2(acc[r][2], cb.y, w2.y);
                fma2(acc[r][3], cb.x, w3.x); fma2(acc[r][3], cb.y, w3.y);
            }
        }
    };

    // ---------------- embed barrier (arrive #1) ----------------
    __syncthreads();                 // g_emb stores block-visible (+ s_w/s_b)
    if (tid == 0) {
        __threadfence();             // cumulative release of the block's stores
        grid_arrive();
        grid_spin(NCTA * 1u);
    }
    __syncthreads();

    // prefetch emb chunk for s=0 into buf0 (g_emb now complete)
    stage_async(buf0, g_emb, EMB, CHUNK_K * team);
    cp_commit();       // pending: {emb_0}

    // ---------------- recurrent loop ----------------
    for (int s = 0; s < SEQ; ++s) {
        const float* hc   = (s == 0) ? h0 : g_hbuf[s & 1];
        const int    e    = s & 1;
        float* bufE = e ? buf1 : buf0;   // holds emb_s (prefetched)
        float* bufH = e ? buf0 : buf1;   // stale, free to overwrite

        #pragma unroll
        for (int r = 0; r < 4; ++r)
            #pragma unroll
            for (int j = 0; j < 4; ++j) acc[r][j] = 0ULL;

        const int kgE = HID + CHUNK_K * team;
        const int kgA = CHUNK_K * team;
        const int kgB = 256 + CHUNK_K * team;

        // ---- emb PART1 (barrier-independent; absorbs skew) ----
        cp_wait0();
        team_bar(bid);
        compute(bufE, kgE, 0, CHUNK_K / 2);

        // ---- barrier WAIT: all CTAs passed step s-1 ----
        if (tid == 0 && s > 0) grid_spin((unsigned)(s + 1) * NCTA);
        __syncthreads();

        // ---- issue hA; emb PART2 hides its latency ----
        stage_async(bufH, hc, HID, kgA);     // pending: {hA}
        cp_commit();
        compute(bufE, kgE, CHUNK_K / 2, CHUNK_K);
        team_bar(bid);                   // team done reading bufE

        // ---- issue hB into bufE; hA compute hides its latency ----
        stage_async(bufE, hc, HID, kgB);     // pending: {hA, hB}
        cp_commit();

        cp_wait1();                      // hA landed
        team_bar(bid);
        compute(bufH, kgA, 0, CHUNK_K);
        team_bar(bid);                   // team done reading bufH

        // ---- prefetch next emb into bufH ----
        {
            int sn = (s + 1 < SEQ) ? s + 1 : s;
            stage_async(bufH, g_emb + (long)sn * (BATCH * EMB), EMB, CHUNK_K * team);
            cp_commit();                 // pending: {hB, embN}
        }

        cp_wait1();                      // hB landed
        team_bar(bid);
        compute(bufE, kgB, 0, CHUNK_K);

        // ---- per-team partial sums -> SMEM slabs ----
        #pragma unroll
        for (int r = 0; r < 4; ++r) {
            int brow = r * 16 + ty;
            #pragma unroll
            for (int j = 0; j < 4; ++j)
                gslab[brow * GPITCH + (tx + 4 * j)] = pairsum(acc[r][j]);
        }
        __syncthreads();

        // ---- activation + state update by owning (b,u) thread ----
        {
            const int base = ab * GPITCH;
            const int T = BATCH * GPITCH;
            float pre_f = s_b[au]
                        + s_g[base + au] + s_g[T + base + au] + s_g[2*T + base + au] + s_g[3*T + base + au];
            float pre_i = s_b[4 + au]
                        + s_g[base+4+au] + s_g[T + base+4+au] + s_g[2*T + base+4+au] + s_g[3*T + base+4+au];
            float pre_c = s_b[8 + au]
                        + s_g[base+8+au] + s_g[T + base+8+au] + s_g[2*T + base+8+au] + s_g[3*T + base+8+au];
            float pre_o = s_b[12 + au]
                        + s_g[base+12+au] + s_g[T + base+12+au] + s_g[2*T + base+12+au] + s_g[3*T + base+12+au];
            float fg = sigf(pre_f);
            float ig = sigf(pre_i);
            float cg = tanhf(pre_c);
            float og = sigf(pre_o);
            c_reg = fg * c_reg + ig * cg;
            float hval = og * tanhf(c_reg);
            g_hbuf[(s + 1) & 1][ab * HID + j0 + au] = hval;
            if (s == SEQ - 1) out[BATCH * OUTD + ab * HID + j0 + au] = hval;
        }
        __syncthreads();                 // h writes block-visible

        // ---- barrier ARRIVE (release by tid0; wait deferred) ----
        if (tid == 0) {
            __threadfence();             // cumulative release of block's h stores
            grid_arrive();               // count -> (s+2)*NCTA
        }
    }

    cp_wait0();   // drain the final (unused) emb prefetch

    // ---------------- dense epilogue ----------------
    // wait for all CTAs' final h (count = 513*NCTA)
    if (tid == 0) grid_spin((unsigned)(SEQ + 1) * NCTA);
    __syncthreads();

    {
        // CTA handles output cols [cta*8, cta*8+8); thread = (b, c4), 2 cols each
        const int c4 = tid & 3;
        const int b  = tid >> 2;           // 0..63
        const float4* hrow = reinterpret_cast<const float4*>(g_hbuf[0] + b * HID);
        #pragma unroll
        for (int j = 0; j < 2; ++j) {
            int col = cta * 8 + c4 + 4 * j;
            if (col < OUTD) {
                float acc4 = __ldg(bd + col);
                #pragma unroll 4
                for (int q = 0; q < HID / 4; ++q) {
                    float4 hv = __ldcv(hrow + q);   // bypass L1 (h from other CTAs)
                    int k = q << 2;
                    acc4 += hv.x * __ldg(Wd + (k    ) * OUTD + col)
                          + hv.y * __ldg(Wd + (k + 1) * OUTD + col)
                          + hv.z * __ldg(Wd + (k + 2) * OUTD + col)
                          + hv.w * __ldg(Wd + (k + 3) * OUTD + col);
                }
                out[b * OUTD + col] = acc4;
            }
        }
    }

    // ---------------- terminal barrier + counter reset ----------------
    __syncthreads();
    if (tid == 0) grid_arrive();         // count -> 514*NCTA
    if (cta == 0 && tid == 0) {
        grid_spin((unsigned)(SEQ + 2) * NCTA);
        *((volatile unsigned int*)&g_bar) = 0u;   // clean for next graph replay
    }
}

// ---------------------------------------------------------------------------
extern "C" void kernel_launch(void* const* d_in, const int* in_sizes, int n_in,
                              void* d_out, int out_size)
{
    const int*   x      = (const int*)  d_in[0];
    const float* hidden = (const float*)d_in[1];
    const float* c      = (const float*)d_in[2];
    const float* ew     = (const float*)d_in[3];
    const float* Wf     = (const float*)d_in[4];
    const float* bf     = (const float*)d_in[5];
    const float* Wi     = (const float*)d_in[6];
    const float* bi     = (const float*)d_in[7];
    const float* Wc     = (const float*)d_in[8];
    const float* bc     = (const float*)d_in[9];
    const float* Wo     = (const float*)d_in[10];
    const float* bo     = (const float*)d_in[11];
    const float* Wd     = (const float*)d_in[12];
    const float* bd     = (const float*)d_in[13];
    float* out = (float*)d_out;   // [B*OUTD output][B*HID hidden]

    const size_t smem_bytes =
        (size_t)(NCOLS * WPAD + NTEAMS * 2 * TEAM_BUF + NTEAMS * BATCH * GPITCH + NCOLS) * sizeof(float);
    cudaFuncSetAttribute(lstm_all_kernel, cudaFuncAttributeMaxDynamicSharedMemorySize, (int)smem_bytes);
    lstm_all_kernel<<<NCTA, NTHREADS, smem_bytes>>>(x, ew, hidden, c,
                                                    Wf, bf, Wi, bi, Wc, bc, Wo, bo,
                                                    Wd, bd, out);
}